// round 10
// baseline (speedup 1.0000x reference)
#include <cuda_runtime.h>

// Problem constants
#define BB   64      // batch
#define NN   8192    // nodes
#define DIN  64
#define DOUT 64
#define DD   10      // embedding dim
#define CC   4       // clients
#define NPC  2048    // nodes per client

#define K1_CHUNKS 32
#define K1_NODES  (NN / K1_CHUNKS)   // 256 nodes per chunk

#define NT 4    // nodes per block in main kernel
#define BT 16   // batch tile in main kernel (4 iterations)
#define ZP64 18 // sZ row stride in u64 units (16 bb + pad 2, even -> 16B aligned)

typedef unsigned long long u64;

// packed f32x2 helpers (FFMA2/FMUL2 path — ptxas never emits these from C++)
__device__ __forceinline__ u64 pk2(float lo, float hi) {
    u64 r; asm("mov.b64 %0,{%1,%2};" : "=l"(r) : "f"(lo), "f"(hi)); return r;
}
__device__ __forceinline__ u64 dup2(float v) { return pk2(v, v); }
__device__ __forceinline__ void f2fma(u64& d, u64 a, u64 b) {
    asm("fma.rn.f32x2 %0,%1,%2,%3;" : "=l"(d) : "l"(a), "l"(b), "l"(d));
}
__device__ __forceinline__ u64 f2mul(u64 a, u64 b) {
    u64 r; asm("mul.rn.f32x2 %0,%1,%2;" : "=l"(r) : "l"(a), "l"(b)); return r;
}
__device__ __forceinline__ float2 u2f(u64 v) {
    float2 f; asm("mov.b64 {%0,%1},%2;" : "=f"(f.x), "=f"(f.y) : "l"(v)); return f;
}

// Scratch (device globals; no runtime allocation allowed)
__device__ float g_part[BB * K1_CHUNKS * DD * DIN];   // 5.2 MB
__device__ float g_sumEH[BB * DD * DIN];              // 160 KB

// ---------------------------------------------------------------------------
// Kernel 1: partial sum_EH. One warp covers full Din (32 lanes x float2),
// acc[DD] single u64 each. tE read as LDS.128 pairs (5 per node).
// ---------------------------------------------------------------------------
__global__ __launch_bounds__(256, 4) void k1_partial(
    const float* __restrict__ x, const float* __restrict__ emb,
    const float* __restrict__ mask, const int* __restrict__ nodes_per)
{
    __shared__ u64   s_tE[K1_NODES * DD];   // dup'd relu(E): 20 KB
    __shared__ int   s_g[K1_NODES];          // 1 KB
    __shared__ float s_red[8][DD * DIN];     // 20 KB

    const int t = threadIdx.x;
    const int b = blockIdx.y, chunk = blockIdx.x;
    const int p0 = chunk * K1_NODES;

    for (int p = t; p < K1_NODES; p += 256) s_g[p] = nodes_per[p0 + p];
    __syncthreads();
    for (int e = t; e < K1_NODES * DD; e += 256) {
        int p = e / DD, d = e - p * DD;
        s_tE[e] = dup2(fmaxf(emb[(size_t)s_g[p] * DD + d], 0.f));
    }
    __syncthreads();

    const int w = t >> 5, lane = t & 31;

    u64 acc[DD];
#pragma unroll
    for (int d = 0; d < DD; d++) acc[d] = 0ull;

    const float* xb = x + (size_t)b * NN * DIN + lane * 2;
    const float* mb = mask + (size_t)b * NN;
    const int base = w * (K1_NODES / 8);   // 32 nodes per warp

#pragma unroll 1
    for (int j = 0; j < K1_NODES / 8; j += 4) {
        int g4[4]; float m4[4]; float2 x4[4];
#pragma unroll
        for (int q = 0; q < 4; q++) g4[q] = s_g[base + j + q];
#pragma unroll
        for (int q = 0; q < 4; q++) {
            m4[q] = __ldg(&mb[g4[q]]);
            x4[q] = *(const float2*)(xb + (size_t)g4[q] * DIN);
        }
#pragma unroll
        for (int q = 0; q < 4; q++) {
            u64 z = f2mul(pk2(x4[q].x, x4[q].y), dup2(m4[q]));
            const u64* te = &s_tE[(base + j + q) * DD];
#pragma unroll
            for (int dp = 0; dp < DD / 2; dp++) {   // LDS.128: two d's at once
                ulonglong2 tv = *(const ulonglong2*)(te + dp * 2);
                f2fma(acc[dp * 2],     tv.x, z);
                f2fma(acc[dp * 2 + 1], tv.y, z);
            }
        }
    }

#pragma unroll
    for (int d = 0; d < DD; d++)
        *(float2*)&s_red[w][d * DIN + lane * 2] = u2f(acc[d]);
    __syncthreads();
    for (int di = t; di < DD * DIN; di += 256) {
        float s = 0.f;
#pragma unroll
        for (int w2 = 0; w2 < 8; w2++) s += s_red[w2][di];
        g_part[((size_t)b * K1_CHUNKS + chunk) * (DD * DIN) + di] = s;
    }
}

// ---------------------------------------------------------------------------
// Kernel 2: reduce chunk partials -> g_sumEH[b,d,i]
// ---------------------------------------------------------------------------
__global__ __launch_bounds__(256) void k2_reduce()
{
    int idx = blockIdx.x * 256 + threadIdx.x;
    if (idx >= BB * DD * DIN) return;
    int b = idx / (DD * DIN), di = idx - b * (DD * DIN);
    float s = 0.f;
#pragma unroll
    for (int k = 0; k < K1_CHUNKS; k++)
        s += g_part[((size_t)b * K1_CHUNKS + k) * (DD * DIN) + di];
    g_sumEH[idx] = s;
}

// ---------------------------------------------------------------------------
// Kernel 3: fused main kernel. 256 threads, NT=4, BT=16, 2 CTAs/SM.
// Z stored PRE-DUPLICATED in [nt][k][bb] layout: GEMM inner loop is
// 3 LDS.128 + 8 FFMA2 per k — zero pack MOVs.
// ---------------------------------------------------------------------------
struct Smem3 {
    float sW[NT * DIN * DOUT];      // 65536 B  [nt][k][o]
    u64   sZ[NT * DIN * ZP64];      // 36864 B  [nt][k][bb(16 dup'd) pad 18]
    u64   stE[NT * DD];             // dup'd relu(E)
    float sE[NT * DD];
    float sbb[NT * DOUT];
    int   sIdx[NT];
};                                   // ~104 KB -> 2 CTAs/SM

__global__ __launch_bounds__(256, 2) void k3_main(
    const float* __restrict__ x, const float* __restrict__ emb,
    const float* __restrict__ mask, const float* __restrict__ wpool,
    const float* __restrict__ bpool, const int* __restrict__ nodes_per,
    float* __restrict__ out)
{
    extern __shared__ __align__(16) char smem_raw[];
    Smem3& S = *reinterpret_cast<Smem3*>(smem_raw);

    const int t = threadIdx.x;
    const int node0 = blockIdx.x * NT;
    const int c = node0 / NPC;

    if (t < NT) S.sIdx[t] = nodes_per[node0 + t];
    __syncthreads();
    if (t < NT * DD) {
        int nt = t / DD, d = t - nt * DD;
        float v = emb[(size_t)S.sIdx[nt] * DD + d];
        S.sE[t] = v;
        S.stE[t] = dup2(fmaxf(v, 0.f));
    }
    __syncthreads();

    // bias: 256 threads cover NT*DOUT = 256 exactly
    {
        int nt = t >> 6, o = t & 63;
        float s = 0.f;
#pragma unroll
        for (int d = 0; d < DD; d++)
            s = fmaf(S.sE[nt * DD + d], bpool[((size_t)c * DD + d) * DOUT + o], s);
        S.sbb[t] = s;
    }

    // W generation (packed): thread owns 4 consecutive floats per pg (4 pgs).
    const float* wpc = wpool + (size_t)c * DD * DIN * DOUT;
#pragma unroll
    for (int pg = 0; pg < 4; pg++) {
        u64 acc[2][NT];
#pragma unroll
        for (int h = 0; h < 2; h++)
#pragma unroll
            for (int nt = 0; nt < NT; nt++) acc[h][nt] = 0ull;
#pragma unroll
        for (int d = 0; d < DD; d++) {
            ulonglong2 wp = *(const ulonglong2*)&wpc[(size_t)d * (DIN * DOUT) + pg * 1024 + t * 4];
#pragma unroll
            for (int nt = 0; nt < NT; nt++) {
                u64 ed = dup2(S.sE[nt * DD + d]);
                f2fma(acc[0][nt], wp.x, ed);
                f2fma(acc[1][nt], wp.y, ed);
            }
        }
#pragma unroll
        for (int nt = 0; nt < NT; nt++) {
            *(float2*)&S.sW[nt * (DIN * DOUT) + pg * 1024 + t * 4]     = u2f(acc[0][nt]);
            *(float2*)&S.sW[nt * (DIN * DOUT) + pg * 1024 + t * 4 + 2] = u2f(acc[1][nt]);
        }
    }
    __syncthreads();

    // ---- Z-gen mapping: 32 i-pairs x 8 bb-pairs ----
    const int i2  = (t & 31) * 2;
    const int bbq = (t >> 5) * 2;

    // ---- GEMM mapping: 8 o-groups x 8 bb-pairs per nt ----
    const int ntg = t >> 6;
    const int tid64 = t & 63;
    const int o0  = (tid64 & 7) * 8;
    const int bb0 = (tid64 >> 3) * 2;

    for (int bt = 0; bt < BB / BT; bt++) {
        const int b0 = bt * BT;

        // ---- Z-gen: j (batch) outer so sumEH is loaded ONCE per batch ----
        float2 zres[NT][2];   // [nt][j]
#pragma unroll
        for (int j = 0; j < 2; j++) {
            const int b = b0 + bbq + j;
            u64 sv[DD];
            const float* se = &g_sumEH[(size_t)b * (DD * DIN) + i2];
#pragma unroll
            for (int d = 0; d < DD; d++) sv[d] = *(const u64*)(se + d * DIN);
            float m4[NT]; float2 xv4[NT];
#pragma unroll
            for (int nt = 0; nt < NT; nt++) {
                int g = S.sIdx[nt];
                m4[nt]  = __ldg(&mask[(size_t)b * NN + g]);
                xv4[nt] = *(const float2*)(x + ((size_t)b * NN + g) * DIN + i2);
            }
#pragma unroll
            for (int nt = 0; nt < NT; nt++) {
                u64 z = pk2(xv4[nt].x * m4[nt], xv4[nt].y * m4[nt]);
#pragma unroll
                for (int d = 0; d < DD; d++)
                    f2fma(z, S.stE[nt * DD + d], sv[d]);   // broadcast LDS.64
                zres[nt][j] = u2f(z);
            }
        }
#pragma unroll
        for (int nt = 0; nt < NT; nt++) {
            ulonglong2 r0, r1;
            r0.x = dup2(zres[nt][0].x); r0.y = dup2(zres[nt][1].x);
            r1.x = dup2(zres[nt][0].y); r1.y = dup2(zres[nt][1].y);
            *(ulonglong2*)&S.sZ[(nt * DIN + i2)     * ZP64 + bbq] = r0;
            *(ulonglong2*)&S.sZ[(nt * DIN + i2 + 1) * ZP64 + bbq] = r1;
        }
        __syncthreads();

        // ---- GEMM: thread tile 2bb x 8o; 3 LDS.128 + 8 FFMA2 per k ----
        u64 acc[2][4];
        {
            ulonglong2 bv0 = *(const ulonglong2*)&S.sbb[ntg * DOUT + o0];
            ulonglong2 bv1 = *(const ulonglong2*)&S.sbb[ntg * DOUT + o0 + 4];
            acc[0][0] = bv0.x; acc[0][1] = bv0.y; acc[0][2] = bv1.x; acc[0][3] = bv1.y;
            acc[1][0] = bv0.x; acc[1][1] = bv0.y; acc[1][2] = bv1.x; acc[1][3] = bv1.y;
        }
        const u64*   zbase = &S.sZ[ntg * DIN * ZP64 + bb0];
        const float* wbase = &S.sW[ntg * (DIN * DOUT) + o0];
#pragma unroll 8
        for (int k = 0; k < DIN; k++) {
            ulonglong2 zz = *(const ulonglong2*)(zbase + k * ZP64);  // dup'd Z[bb0], Z[bb0+1]
            ulonglong2 w0 = *(const ulonglong2*)(wbase + (size_t)k * DOUT);
            ulonglong2 w1 = *(const ulonglong2*)(wbase + (size_t)k * DOUT + 4);
            f2fma(acc[0][0], zz.x, w0.x); f2fma(acc[0][1], zz.x, w0.y);
            f2fma(acc[0][2], zz.x, w1.x); f2fma(acc[0][3], zz.x, w1.y);
            f2fma(acc[1][0], zz.y, w0.x); f2fma(acc[1][1], zz.y, w0.y);
            f2fma(acc[1][2], zz.y, w1.x); f2fma(acc[1][3], zz.y, w1.y);
        }
#pragma unroll
        for (int j = 0; j < 2; j++) {
            int b = b0 + bb0 + j;
            float* row = out + ((size_t)b * NN + node0 + ntg) * DOUT + o0;
            float2 p0 = u2f(acc[j][0]), p1 = u2f(acc[j][1]);
            float2 p2 = u2f(acc[j][2]), p3 = u2f(acc[j][3]);
            *(float4*)row       = make_float4(p0.x, p0.y, p1.x, p1.y);
            *(float4*)(row + 4) = make_float4(p2.x, p2.y, p3.x, p3.y);
        }
        __syncthreads();
    }
}

// ---------------------------------------------------------------------------
extern "C" void kernel_launch(void* const* d_in, const int* in_sizes, int n_in,
                              void* d_out, int out_size)
{
    const float* x     = (const float*)d_in[0];
    const float* emb   = (const float*)d_in[1];
    // d_in[2] = poly_coefficients (unused in sprtrelu mode)
    const float* mask  = (const float*)d_in[3];
    const float* wpool = (const float*)d_in[4];
    const float* bpool = (const float*)d_in[5];
    const int*   nodes = (const int*)d_in[6];
    float* out = (float*)d_out;

    cudaFuncSetAttribute(k3_main, cudaFuncAttributeMaxDynamicSharedMemorySize,
                         (int)sizeof(Smem3));

    dim3 g1(K1_CHUNKS, BB);
    k1_partial<<<g1, 256>>>(x, emb, mask, nodes);

    int tot = BB * DD * DIN;
    k2_reduce<<<(tot + 255) / 256, 256>>>();

    k3_main<<<NN / NT, 256, sizeof(Smem3)>>>(x, emb, mask, wpool, bpool, nodes, out);
}

// round 12
// speedup vs baseline: 1.0165x; 1.0165x over previous
#include <cuda_runtime.h>

// Problem constants
#define BB   64
#define NN   8192
#define DIN  64
#define DOUT 64
#define DD   10
#define CC   4
#define NPC  2048

#define K1_CHUNKS 32
#define K1_NODES  (NN / K1_CHUNKS)

#define NTM  4      // nodes per CTA in HMMA kernel (2 pairs)

typedef unsigned long long u64;
typedef unsigned int u32;

// ---- packed f32x2 helpers ----
__device__ __forceinline__ u64 pk2(float lo, float hi) {
    u64 r; asm("mov.b64 %0,{%1,%2};" : "=l"(r) : "f"(lo), "f"(hi)); return r;
}
__device__ __forceinline__ u64 dup2(float v) { return pk2(v, v); }
__device__ __forceinline__ void f2fma(u64& d, u64 a, u64 b) {
    asm("fma.rn.f32x2 %0,%1,%2,%3;" : "=l"(d) : "l"(a), "l"(b), "l"(d));
}
__device__ __forceinline__ u64 f2mul(u64 a, u64 b) {
    u64 r; asm("mul.rn.f32x2 %0,%1,%2;" : "=l"(r) : "l"(a), "l"(b)); return r;
}
__device__ __forceinline__ float2 u2f(u64 v) {
    float2 f; asm("mov.b64 {%0,%1},%2;" : "=f"(f.x), "=f"(f.y) : "l"(v)); return f;
}

__device__ __forceinline__ u32 smem_u32(const void* p) {
    u32 a; asm("{ .reg .u64 t; cvta.to.shared.u64 t, %1; cvt.u32.u64 %0, t; }" : "=r"(a) : "l"(p));
    return a;
}

// word = {lo16: bf16(x0), hi16: bf16(x1)}
#define CVT_BF16X2(res, x0, x1) \
    asm("cvt.rn.satfinite.bf16x2.f32 %0, %1, %2;" : "=r"(res) : "f"(x1), "f"(x0))

__device__ __forceinline__ u32 sw128(u32 off) { return off ^ ((off >> 3) & 0x70); }

// ---- warp MMA (sm_80+ path; no arch-specific suffix needed) ----
__device__ __forceinline__ void hmma(float* c, const u32* a, u32 b0, u32 b1) {
    asm("mma.sync.aligned.m16n8k16.row.col.f32.bf16.bf16.f32 "
        "{%0,%1,%2,%3}, {%4,%5,%6,%7}, {%8,%9}, {%0,%1,%2,%3};"
        : "+f"(c[0]), "+f"(c[1]), "+f"(c[2]), "+f"(c[3])
        : "r"(a[0]), "r"(a[1]), "r"(a[2]), "r"(a[3]), "r"(b0), "r"(b1));
}
__device__ __forceinline__ void ldmA(u32* r, u32 addr) {
    asm volatile("ldmatrix.sync.aligned.m8n8.x4.shared.b16 {%0,%1,%2,%3}, [%4];"
        : "=r"(r[0]), "=r"(r[1]), "=r"(r[2]), "=r"(r[3]) : "r"(addr));
}
__device__ __forceinline__ void ldmB(u32& r0, u32& r1, u32 addr) {
    asm volatile("ldmatrix.sync.aligned.m8n8.x2.trans.shared.b16 {%0,%1}, [%2];"
        : "=r"(r0), "=r"(r1) : "r"(addr));
}

// Scratch
__device__ float g_part[BB * K1_CHUNKS * DD * DIN];
__device__ float g_sumEH[BB * DD * DIN];

// ---------------------------------------------------------------------------
// Kernel 1: partial sum_EH (best measured form, ~47us)
// ---------------------------------------------------------------------------
__global__ __launch_bounds__(256, 4) void k1_partial(
    const float* __restrict__ x, const float* __restrict__ emb,
    const float* __restrict__ mask, const int* __restrict__ nodes_per)
{
    __shared__ u64   s_tE[K1_NODES * DD];
    __shared__ int   s_g[K1_NODES];
    __shared__ float s_red[8][DD * DIN];

    const int t = threadIdx.x;
    const int b = blockIdx.y, chunk = blockIdx.x;
    const int p0 = chunk * K1_NODES;

    for (int p = t; p < K1_NODES; p += 256) s_g[p] = nodes_per[p0 + p];
    __syncthreads();
    for (int e = t; e < K1_NODES * DD; e += 256) {
        int p = e / DD, d = e - p * DD;
        s_tE[e] = dup2(fmaxf(emb[(size_t)s_g[p] * DD + d], 0.f));
    }
    __syncthreads();

    const int w = t >> 5, lane = t & 31;
    u64 acc[DD];
#pragma unroll
    for (int d = 0; d < DD; d++) acc[d] = 0ull;

    const float* xb = x + (size_t)b * NN * DIN + lane * 2;
    const float* mb = mask + (size_t)b * NN;
    const int base = w * (K1_NODES / 8);

#pragma unroll 1
    for (int j = 0; j < K1_NODES / 8; j += 4) {
        int g4[4]; float m4[4]; float2 x4[4];
#pragma unroll
        for (int q = 0; q < 4; q++) g4[q] = s_g[base + j + q];
#pragma unroll
        for (int q = 0; q < 4; q++) {
            m4[q] = __ldg(&mb[g4[q]]);
            x4[q] = *(const float2*)(xb + (size_t)g4[q] * DIN);
        }
#pragma unroll
        for (int q = 0; q < 4; q++) {
            u64 z = f2mul(pk2(x4[q].x, x4[q].y), dup2(m4[q]));
            const u64* te = &s_tE[(base + j + q) * DD];
#pragma unroll
            for (int dp = 0; dp < DD / 2; dp++) {
                ulonglong2 tv = *(const ulonglong2*)(te + dp * 2);
                f2fma(acc[dp * 2],     tv.x, z);
                f2fma(acc[dp * 2 + 1], tv.y, z);
            }
        }
    }
#pragma unroll
    for (int d = 0; d < DD; d++)
        *(float2*)&s_red[w][d * DIN + lane * 2] = u2f(acc[d]);
    __syncthreads();
    for (int di = t; di < DD * DIN; di += 256) {
        float s = 0.f;
#pragma unroll
        for (int w2 = 0; w2 < 8; w2++) s += s_red[w2][di];
        g_part[((size_t)b * K1_CHUNKS + chunk) * (DD * DIN) + di] = s;
    }
}

__global__ __launch_bounds__(256) void k2_reduce()
{
    int idx = blockIdx.x * 256 + threadIdx.x;
    if (idx >= BB * DD * DIN) return;
    int b = idx / (DD * DIN), di = idx - b * (DD * DIN);
    float s = 0.f;
#pragma unroll
    for (int k = 0; k < K1_CHUNKS; k++)
        s += g_part[((size_t)b * K1_CHUNKS + k) * (DD * DIN) + di];
    g_sumEH[idx] = s;
}

// ---------------------------------------------------------------------------
// Kernel 3 (warp HMMA): per CTA 4 nodes = 2 pairs. Per node a 64x64x64 GEMM
// out[b,n,o] = Z[b,n,:] @ W[n] + bias, via mma.sync bf16 split precision:
//   D = Zhi*Whi + Zhi*Wlo + Zlo*Whi   (fp32 accumulate in registers)
// ---------------------------------------------------------------------------
#define OFF_IDX  0
#define OFF_E    64
#define OFF_TE   256
#define OFF_BIAS 512      // [4][64] f32 -> ends 1536
#define OFF_WHI  2048     // 4 x 8KB (64k x 64o bf16, 128B rows, sw128)
#define OFF_WLO  34816    // 4 x 8KB
#define OFF_ZHI  67584    // 2 x 8KB (64b x 64k bf16)
#define OFF_ZLO  83968    // 2 x 8KB
#define SMEM_K3  100352   // ~98KB -> 2 CTAs/SM

__global__ __launch_bounds__(256, 2) void k3_hmma(
    const float* __restrict__ x, const float* __restrict__ emb,
    const float* __restrict__ mask, const float* __restrict__ wpool,
    const float* __restrict__ bpool, const int* __restrict__ nodes_per,
    float* __restrict__ out)
{
    extern __shared__ __align__(1024) char smem[];
    const u32 sb = smem_u32(smem);
    const int t = threadIdx.x;
    const int node0 = blockIdx.x * NTM;
    const int c = node0 / NPC;

    int*   sIdx  = (int*)(smem + OFF_IDX);
    float* sE    = (float*)(smem + OFF_E);
    float* stE   = (float*)(smem + OFF_TE);
    float* sBias = (float*)(smem + OFF_BIAS);

    if (t < NTM) sIdx[t] = nodes_per[node0 + t];
    __syncthreads();
    if (t < NTM * DD) {
        int nt = t / DD, d = t - nt * DD;
        float v = emb[(size_t)sIdx[nt] * DD + d];
        sE[t] = v;
        stE[t] = fmaxf(v, 0.f);
    }
    __syncthreads();

    // bias (fp32, exact): 256 threads = 4 nodes x 64 o
    {
        int nt = t >> 6, o = t & 63;
        float s = 0.f;
#pragma unroll
        for (int d = 0; d < DD; d++)
            s = fmaf(sE[nt * DD + d], bpool[((size_t)c * DD + d) * DOUT + o], s);
        sBias[t] = s;
    }

    // ---- W-gen: wpool read once per CTA; W[n][k=i][o] bf16 hi/lo, sw128 ----
    {
        const float* wpc = wpool + (size_t)c * DD * DIN * DOUT;
        const int o4 = (t & 15) * 4, ib = t >> 4;   // 4x4 cell of (i,o)
        float acc[NTM][4][4];
#pragma unroll
        for (int n = 0; n < NTM; n++)
#pragma unroll
            for (int r = 0; r < 4; r++)
#pragma unroll
                for (int q = 0; q < 4; q++) acc[n][r][q] = 0.f;
#pragma unroll
        for (int d = 0; d < DD; d++) {
            float4 wv[4];
#pragma unroll
            for (int r = 0; r < 4; r++)
                wv[r] = *(const float4*)&wpc[(size_t)d * (DIN * DOUT) + (ib * 4 + r) * DOUT + o4];
#pragma unroll
            for (int n = 0; n < NTM; n++) {
                float e = sE[n * DD + d];
#pragma unroll
                for (int r = 0; r < 4; r++) {
                    acc[n][r][0] = fmaf(e, wv[r].x, acc[n][r][0]);
                    acc[n][r][1] = fmaf(e, wv[r].y, acc[n][r][1]);
                    acc[n][r][2] = fmaf(e, wv[r].z, acc[n][r][2]);
                    acc[n][r][3] = fmaf(e, wv[r].w, acc[n][r][3]);
                }
            }
        }
#pragma unroll
        for (int n = 0; n < NTM; n++)
#pragma unroll
            for (int r = 0; r < 4; r++) {
                int k = ib * 4 + r;
                u32 sw = sw128((u32)(k * 128 + o4 * 2));
                u32 h0, h1, g0, g1;
                CVT_BF16X2(h0, acc[n][r][0], acc[n][r][1]);
                CVT_BF16X2(h1, acc[n][r][2], acc[n][r][3]);
                float l0 = acc[n][r][0] - __uint_as_float(h0 << 16);
                float l1 = acc[n][r][1] - __uint_as_float(h0 & 0xffff0000u);
                float l2 = acc[n][r][2] - __uint_as_float(h1 << 16);
                float l3 = acc[n][r][3] - __uint_as_float(h1 & 0xffff0000u);
                CVT_BF16X2(g0, l0, l1);
                CVT_BF16X2(g1, l2, l3);
                *(u64*)(smem + OFF_WHI + n * 8192 + sw) = (u64)h0 | ((u64)h1 << 32);
                *(u64*)(smem + OFF_WLO + n * 8192 + sw) = (u64)g0 | ((u64)g1 << 32);
            }
    }
    __syncthreads();

    // warp mapping for MMA: 8 warps = (node-of-pair) x (o-half) x (m-half)
    const int w = t >> 5, lane = t & 31;
    const int lnw = w & 1, oh = (w >> 1) & 1, mh = w >> 2;
    const int arow = mh * 32 + (lane & 15);
    const int achunk = (lane >> 4) * 16;
    const int brow = lane & 15;

    for (int p = 0; p < 2; p++) {
        // ---- Z-gen: thread = (b, k-quarter); serves BOTH pair nodes ----
        {
            const int b = t & 63, k0 = (t >> 6) * 16;
            const int gA = sIdx[p * 2], gB = sIdx[p * 2 + 1];
            const float mA = __ldg(&mask[(size_t)b * NN + gA]);
            const float mB = __ldg(&mask[(size_t)b * NN + gB]);
            const float4* xA = (const float4*)(x + ((size_t)b * NN + gA) * DIN + k0);
            const float4* xB = (const float4*)(x + ((size_t)b * NN + gB) * DIN + k0);
            u64 z0[8], z1[8];
            {
                u64 mdA = dup2(mA), mdB = dup2(mB);
#pragma unroll
                for (int i = 0; i < 4; i++) {
                    float4 a = xA[i];
                    z0[2 * i]     = f2mul(pk2(a.x, a.y), mdA);
                    z0[2 * i + 1] = f2mul(pk2(a.z, a.w), mdA);
                    float4 bv = xB[i];
                    z1[2 * i]     = f2mul(pk2(bv.x, bv.y), mdB);
                    z1[2 * i + 1] = f2mul(pk2(bv.z, bv.w), mdB);
                }
            }
            const float* se = g_sumEH + (size_t)b * (DD * DIN) + k0;
#pragma unroll
            for (int d = 0; d < DD; d++) {
                ulonglong2 sa = *(const ulonglong2*)(se + d * DIN);
                ulonglong2 sbv = *(const ulonglong2*)(se + d * DIN + 4);
                ulonglong2 sc = *(const ulonglong2*)(se + d * DIN + 8);
                ulonglong2 sd = *(const ulonglong2*)(se + d * DIN + 12);
                u64 e0 = dup2(stE[(p * 2) * DD + d]);
                u64 e1 = dup2(stE[(p * 2 + 1) * DD + d]);
                f2fma(z0[0], e0, sa.x);  f2fma(z1[0], e1, sa.x);
                f2fma(z0[1], e0, sa.y);  f2fma(z1[1], e1, sa.y);
                f2fma(z0[2], e0, sbv.x); f2fma(z1[2], e1, sbv.x);
                f2fma(z0[3], e0, sbv.y); f2fma(z1[3], e1, sbv.y);
                f2fma(z0[4], e0, sc.x);  f2fma(z1[4], e1, sc.x);
                f2fma(z0[5], e0, sc.y);  f2fma(z1[5], e1, sc.y);
                f2fma(z0[6], e0, sd.x);  f2fma(z1[6], e1, sd.x);
                f2fma(z0[7], e0, sd.y);  f2fma(z1[7], e1, sd.y);
            }
#pragma unroll
            for (int j = 0; j < 8; j++) {
                u32 sw = sw128((u32)(b * 128 + (k0 + 2 * j) * 2));
                float2 f0 = u2f(z0[j]);
                u32 h, l;
                CVT_BF16X2(h, f0.x, f0.y);
                float l0 = f0.x - __uint_as_float(h << 16);
                float l1 = f0.y - __uint_as_float(h & 0xffff0000u);
                CVT_BF16X2(l, l0, l1);
                *(u32*)(smem + OFF_ZHI + sw) = h;
                *(u32*)(smem + OFF_ZLO + sw) = l;
                float2 f1 = u2f(z1[j]);
                CVT_BF16X2(h, f1.x, f1.y);
                l0 = f1.x - __uint_as_float(h << 16);
                l1 = f1.y - __uint_as_float(h & 0xffff0000u);
                CVT_BF16X2(l, l0, l1);
                *(u32*)(smem + OFF_ZHI + 8192 + sw) = h;
                *(u32*)(smem + OFF_ZLO + 8192 + sw) = l;
            }
        }
        __syncthreads();

        // ---- MMA: 3 split-precision passes, fp32 reg accumulation ----
        const int node = p * 2 + lnw;            // local node 0..3
        float cacc[2][4][4];
#pragma unroll
        for (int mt = 0; mt < 2; mt++)
#pragma unroll
            for (int nt = 0; nt < 4; nt++)
#pragma unroll
                for (int q = 0; q < 4; q++) cacc[mt][nt][q] = 0.f;

        const u32 zhi = sb + OFF_ZHI + lnw * 8192;
        const u32 zlo = sb + OFF_ZLO + lnw * 8192;
        const u32 whi = sb + OFF_WHI + node * 8192;
        const u32 wlo = sb + OFF_WLO + node * 8192;

#pragma unroll
        for (int pass = 0; pass < 3; pass++) {
            const u32 ab = (pass == 2) ? zlo : zhi;
            const u32 bbs = (pass == 1) ? wlo : whi;
#pragma unroll
            for (int s = 0; s < 4; s++) {
                u32 a0[4], a1[4];
                ldmA(a0, ab + sw128((u32)(arow * 128 + s * 32 + achunk)));
                ldmA(a1, ab + sw128((u32)((arow + 16) * 128 + s * 32 + achunk)));
#pragma unroll
                for (int nt = 0; nt < 4; nt++) {
                    u32 b0, b1;
                    ldmB(b0, b1, bbs + sw128((u32)((s * 16 + brow) * 128 + (oh * 32 + nt * 8) * 2)));
                    hmma(cacc[0][nt], a0, b0, b1);
                    hmma(cacc[1][nt], a1, b0, b1);
                }
            }
        }

        // ---- epilogue: add bias, store ----
        {
            const int gq = lane >> 2, tq = lane & 3;
#pragma unroll
            for (int mt = 0; mt < 2; mt++)
#pragma unroll
                for (int nt = 0; nt < 4; nt++) {
                    int row = mh * 32 + mt * 16 + gq;
                    int o = oh * 32 + nt * 8 + tq * 2;
                    float b0v = sBias[node * DOUT + o];
                    float b1v = sBias[node * DOUT + o + 1];
                    float* r0 = out + ((size_t)row * NN + node0 + node) * DOUT + o;
                    *(float2*)r0 = make_float2(cacc[mt][nt][0] + b0v, cacc[mt][nt][1] + b1v);
                    float* r1 = r0 + (size_t)8 * NN * DOUT;
                    *(float2*)r1 = make_float2(cacc[mt][nt][2] + b0v, cacc[mt][nt][3] + b1v);
                }
        }
        __syncthreads();
    }
}

// ---------------------------------------------------------------------------
extern "C" void kernel_launch(void* const* d_in, const int* in_sizes, int n_in,
                              void* d_out, int out_size)
{
    const float* x     = (const float*)d_in[0];
    const float* emb   = (const float*)d_in[1];
    const float* mask  = (const float*)d_in[3];
    const float* wpool = (const float*)d_in[4];
    const float* bpool = (const float*)d_in[5];
    const int*   nodes = (const int*)d_in[6];
    float* out = (float*)d_out;

    cudaFuncSetAttribute(k3_hmma, cudaFuncAttributeMaxDynamicSharedMemorySize, SMEM_K3);

    dim3 g1(K1_CHUNKS, BB);
    k1_partial<<<g1, 256>>>(x, emb, mask, nodes);

    int tot = BB * DD * DIN;
    k2_reduce<<<(tot + 255) / 256, 256>>>();

    k3_hmma<<<NN / NTM, 256, SMEM_K3>>>(x, emb, mask, wpool, bpool, nodes, out);
}